// round 1
// baseline (speedup 1.0000x reference)
#include <cuda_runtime.h>
#include <cstdint>

// StructuredConnection: y = x @ (W*M)^T + bias
// x: [16384, 4096] fp32, W/M: [4096, 4096] fp32, bias: [4096]
// Mask is banded: output o uses inputs (81*o + j) % 4096, j = 0..80.
// Permutation: c = 81*o mod 4096  <=>  o = 2225*c mod 4096.
// In c-order the problem is a perfect banded matmul: output-c uses inputs [c, c+81).

#define BATCH   16384
#define IOF     4096      // in_features == out_features
#define CPN     81        // connections per neuron
#define INV81   2225      // 81^-1 mod 4096
#define CT      64        // c-tile (outputs per block, permuted order)
#define BT      128       // batch tile per block
#define PW      88        // padded p-range per warp: p = cc + j, cc<8, j<81 -> 0..87
#define XW      148       // xs row stride (>=144 needed; 148 = 4-mult, 37 odd 16B-granules -> no LDS.128 conflicts)
#define THREADS 256

// Scratch (device globals are the sanctioned way to get scratch; no allocs in kernel_launch).
__device__ float g_wp[IOF * CPN];                  // packed band weights, c-order: [c][j]
__device__ float g_outT[(size_t)IOF * BATCH];      // transposed output: [o][b]

// ---------------- prep: pack (W*M) along the band, permuted to c-order ----------------
__global__ void prep_kernel(const float* __restrict__ w, const float* __restrict__ m) {
    int idx = blockIdx.x * blockDim.x + threadIdx.x;
    if (idx >= IOF * CPN) return;
    int c = idx / CPN;
    int j = idx - c * CPN;
    int o = (INV81 * c) & (IOF - 1);
    int col = (c + j) & (IOF - 1);
    size_t off = (size_t)o * IOF + col;
    g_wp[idx] = w[off] * m[off];   // mask is 1.0 at band positions
}

// ---------------- main: banded matmul in permuted (c) order ----------------
// Block: 8 warps. Warp w owns c-sublane [8w, 8w+8). Thread lane l owns batch rows
// {l, l+32, l+64, l+96}. Each thread keeps 8x4 fp32 accumulators.
// ws2 holds per-block-c weights shifted by (c&7) and zero padded so the inner loop is
// fully regular: acc[cc][bb] += ws2[8w+cc][p] * xs[row][8w+p], p = 0..87.
__global__ void __launch_bounds__(THREADS, 2) main_kernel(const float* __restrict__ x) {
    extern __shared__ float smem[];
    float* xs  = smem;               // [BT][XW]
    float* ws2 = smem + BT * XW;     // [CT][PW]

    const int tid  = threadIdx.x;
    const int lane = tid & 31;
    const int w    = tid >> 5;
    const int c0   = blockIdx.x * CT;
    const int b0   = blockIdx.y * BT;

    // Load x tile: rows b0..b0+127, cols (c0 .. c0+147) mod 4096. Coalesced.
    for (int r = w; r < BT; r += 8) {
        const float* xrow = x + (size_t)(b0 + r) * IOF;
        for (int i = lane; i < XW; i += 32)
            xs[r * XW + i] = xrow[(c0 + i) & (IOF - 1)];
    }
    // Load shifted/zero-padded weights: ws2[ccb][p] = wp[c0+ccb][p - (ccb&7)] or 0.
    for (int idx = tid; idx < CT * PW; idx += THREADS) {
        int ccb = idx / PW;
        int p   = idx - ccb * PW;
        int j   = p - (ccb & 7);
        float v = 0.0f;
        if (j >= 0 && j < CPN) v = g_wp[(c0 + ccb) * CPN + j];
        ws2[idx] = v;
    }
    __syncthreads();

    float acc[8][4];
#pragma unroll
    for (int cc = 0; cc < 8; cc++)
#pragma unroll
        for (int bb = 0; bb < 4; bb++) acc[cc][bb] = 0.0f;

    const int cwo = w * 8;
    const float* xbase = xs + lane * XW + cwo;     // row = lane + 32*bb handled via +32*XW
    const float* wbase = ws2 + cwo * PW;

#pragma unroll 2
    for (int p4 = 0; p4 < PW; p4 += 4) {
        float4 xv[4];
#pragma unroll
        for (int bb = 0; bb < 4; bb++)
            xv[bb] = *reinterpret_cast<const float4*>(xbase + bb * (32 * XW) + p4);
#pragma unroll
        for (int cc = 0; cc < 8; cc++) {
            float4 wv = *reinterpret_cast<const float4*>(wbase + cc * PW + p4);
#pragma unroll
            for (int bb = 0; bb < 4; bb++) {
                acc[cc][bb] = fmaf(wv.x, xv[bb].x, acc[cc][bb]);
                acc[cc][bb] = fmaf(wv.y, xv[bb].y, acc[cc][bb]);
                acc[cc][bb] = fmaf(wv.z, xv[bb].z, acc[cc][bb]);
                acc[cc][bb] = fmaf(wv.w, xv[bb].w, acc[cc][bb]);
            }
        }
    }

    // Store transposed: outT[o][b], warp lanes map to consecutive b -> 128B coalesced.
#pragma unroll
    for (int cc = 0; cc < 8; cc++) {
        int o = (INV81 * (c0 + cwo + cc)) & (IOF - 1);
        float* dst = g_outT + (size_t)o * BATCH + b0 + lane;
#pragma unroll
        for (int bb = 0; bb < 4; bb++)
            dst[32 * bb] = acc[cc][bb];
    }
}

// ---------------- transpose + bias: out[b][o] = outT[o][b] + bias[o] ----------------
__global__ void transpose_kernel(const float* __restrict__ bias, float* __restrict__ out) {
    __shared__ float t[32][33];
    const int tx = threadIdx.x, ty = threadIdx.y;
    const int o0 = blockIdx.x * 32;
    const int b0 = blockIdx.y * 32;
#pragma unroll
    for (int k = ty; k < 32; k += 8)
        t[k][tx] = g_outT[(size_t)(o0 + k) * BATCH + b0 + tx];   // coalesced along b
    __syncthreads();
    float bv = bias[o0 + tx];
#pragma unroll
    for (int k = ty; k < 32; k += 8)
        out[(size_t)(b0 + k) * IOF + o0 + tx] = t[tx][k] + bv;   // coalesced along o
}

extern "C" void kernel_launch(void* const* d_in, const int* in_sizes, int n_in,
                              void* d_out, int out_size) {
    const float* x    = (const float*)d_in[0];
    const float* wgt  = (const float*)d_in[1];
    const float* bias = (const float*)d_in[2];
    const float* mask = (const float*)d_in[3];
    float* out = (float*)d_out;

    const int smem_bytes = (BT * XW + CT * PW) * (int)sizeof(float);   // 98304
    cudaFuncSetAttribute(main_kernel, cudaFuncAttributeMaxDynamicSharedMemorySize, smem_bytes);

    prep_kernel<<<(IOF * CPN + 255) / 256, 256>>>(wgt, mask);
    main_kernel<<<dim3(IOF / CT, BATCH / BT), THREADS, smem_bytes>>>(x);
    transpose_kernel<<<dim3(IOF / 32, BATCH / 32), dim3(32, 8)>>>(bias, out);
}

// round 3
// speedup vs baseline: 3.4423x; 3.4423x over previous
#include <cuda_runtime.h>
#include <cstdint>

// StructuredConnection via warp-level tf32 mma.sync banded GEMM (plain PTX, no 100a features).
// x:[16384,4096] f32. Mask banded: out o uses inputs (81*o+j)%4096, j<81.
// c = 81*o mod 4096  <=>  o = 2225*c mod 4096. In c-order: out_c = sum_j wp[c][j]*x[(c+j)&4095].
// Per c-tile (128 wide): each warp handles a 32-wide c-slice whose band spans K=112.

#define BATCH   16384
#define IOF     4096
#define CPN     81
#define INV81   2225
#define NT      128          // c per CTA
#define MH      64           // batch rows per half-tile
#define KWIN    208          // k window per CTA tile
#define SX      212          // xs row stride (floats); 212 % 32 == 20 -> conflict-free A frags
#define SB      136          // Bs row stride (floats); 136 % 32 == 8  -> conflict-free B frags
#define STW     68           // stage row stride (floats); 68 % 32 == 4 -> conflict-free staging
#define GY      4
#define NHALF   64           // (BATCH/GY)/MH
#define THREADS 256
#define XS_BYTES (MH*SX*4)               // 54272
#define BS_BYTES (KWIN*SB*4)             // 113152
#define OFF_XS0  0
#define OFF_XS1  XS_BYTES
#define OFF_BS   (2*XS_BYTES)
#define SMEM_TOTAL (2*XS_BYTES + BS_BYTES)   // 221696

__device__ uint32_t g_bw[32 * KWIN * SB];        // per-c-tile padded B (tf32 bits), [ct][k][n]
__device__ float    g_outT[(size_t)IOF * BATCH]; // transposed output: [o][b]

// ---------------- helpers ----------------
__device__ __forceinline__ uint32_t cvt_tf32(float x) {
    uint32_t u; asm("cvt.rna.tf32.f32 %0, %1;" : "=r"(u) : "f"(x)); return u;
}
__device__ __forceinline__ uint32_t smem_u32(const void* p) {
    uint32_t a; asm("{ .reg .u64 t; cvta.to.shared.u64 t, %1; cvt.u32.u64 %0, t; }" : "=r"(a) : "l"(p));
    return a;
}
#define CP16(d, s) asm volatile("cp.async.cg.shared.global [%0], [%1], 16;" :: "r"(d), "l"(s))
#define CPC()      asm volatile("cp.async.commit_group;" ::: "memory")
#define CPW1()     asm volatile("cp.async.wait_group 1;" ::: "memory")

__device__ __forceinline__ void mma8(float* d, const uint32_t* a, const uint32_t* b) {
    asm volatile(
        "mma.sync.aligned.m16n8k8.row.col.f32.tf32.tf32.f32 "
        "{%0,%1,%2,%3}, {%4,%5,%6,%7}, {%8,%9}, {%0,%1,%2,%3};"
        : "+f"(d[0]), "+f"(d[1]), "+f"(d[2]), "+f"(d[3])
        : "r"(a[0]), "r"(a[1]), "r"(a[2]), "r"(a[3]), "r"(b[0]), "r"(b[1]));
}

// ---------------- prep: tf32-rounded, band-expanded B in [ct][k][n] padded layout ----------------
__global__ void prep_kernel(const float* __restrict__ w, const float* __restrict__ m) {
    int idx = blockIdx.x * blockDim.x + threadIdx.x;
    if (idx >= 32 * KWIN * SB) return;
    int ct = idx / (KWIN * SB);
    int r  = idx - ct * (KWIN * SB);
    int k  = r / SB;
    int n  = r - k * SB;
    uint32_t u = 0;
    int j = k - n;
    if (n < NT && j >= 0 && j < CPN) {
        int c   = ct * NT + n;
        int o   = (INV81 * c) & (IOF - 1);
        int col = (c + j) & (IOF - 1);
        size_t off = (size_t)o * IOF + col;
        u = cvt_tf32(w[off] * m[off]);
    }
    g_bw[idx] = u;
}

// ---------------- main kernel ----------------
__global__ void __launch_bounds__(THREADS) main_kernel(const float* __restrict__ x) {
    extern __shared__ char smem[];
    const uint32_t sb0 = smem_u32(smem);
    const int tid  = threadIdx.x;
    const int lane = tid & 31;
    const int wid  = tid >> 5;
    const int t4   = lane >> 2;     // 0..7
    const int tm   = lane & 3;      // 0..3
    const int ct   = blockIdx.x;
    const int c0   = ct * NT;
    const int browCTA = blockIdx.y * (BATCH / GY);

    // B tile: straight 16B async copy of the pre-padded [208][136] block.
    {
        const char* src = reinterpret_cast<const char*>(g_bw + (size_t)ct * KWIN * SB);
#pragma unroll
        for (int i = 0; i < 28; i++) {
            int q = i * THREADS + tid;
            if (q * 16 < BS_BYTES) CP16(sb0 + OFF_BS + q * 16, src + q * 16);
        }
    }
    // x half-tile loader: 64 rows x 208 floats (52 16B chunks/row), 3328 chunks = 13/thread.
    auto load_x = [&](int h, uint32_t dstoff) {
        const int brow0 = browCTA + h * MH;
#pragma unroll
        for (int i = 0; i < 13; i++) {
            int q   = i * THREADS + tid;
            int row = q / 52;
            int chk = q - row * 52;
            const float* s = x + (size_t)(brow0 + row) * IOF + ((c0 + chk * 4) & (IOF - 1));
            CP16(sb0 + dstoff + row * (SX * 4) + chk * 16, s);
        }
    };
    load_x(0, OFF_XS0);
    CPC();                                      // group0: B + x0

    const int q  = wid & 3;                     // n-quarter
    const int mw = wid >> 2;                    // m-half
    const int m0 = mw * 32;
    const int n0 = q * 32;

    for (int h = 0; h < NHALF; h++) {
        const uint32_t bufoff = (h & 1) ? OFF_XS1 : OFF_XS0;
        if (h + 1 < NHALF) load_x(h + 1, (h & 1) ? OFF_XS0 : OFF_XS1);
        CPC();
        CPW1();                                 // x[h] (and B) resident
        __syncthreads();

        float d[2][4][4];
#pragma unroll
        for (int mi = 0; mi < 2; mi++)
#pragma unroll
            for (int ni = 0; ni < 4; ni++)
#pragma unroll
                for (int r = 0; r < 4; r++) d[mi][ni][r] = 0.0f;

        const float*    xsb = reinterpret_cast<const float*>(smem + bufoff) + (m0 + t4) * SX + 32 * q + tm;
        const uint32_t* bsb = reinterpret_cast<const uint32_t*>(smem + OFF_BS) + (32 * q + tm) * SB + n0 + t4;

#pragma unroll
        for (int s = 0; s < 14; s++) {          // K = 112 per warp
            uint32_t a[2][4], b[4][2];
#pragma unroll
            for (int mi = 0; mi < 2; mi++) {
                const float* xp = xsb + mi * 16 * SX + s * 8;
                a[mi][0] = cvt_tf32(xp[0]);
                a[mi][1] = cvt_tf32(xp[8 * SX]);
                a[mi][2] = cvt_tf32(xp[4]);
                a[mi][3] = cvt_tf32(xp[8 * SX + 4]);
            }
            const uint32_t* bp = bsb + s * 8 * SB;
#pragma unroll
            for (int ni = 0; ni < 4; ni++) {
                b[ni][0] = bp[ni * 8];
                b[ni][1] = bp[4 * SB + ni * 8];
            }
#pragma unroll
            for (int mi = 0; mi < 2; mi++)
#pragma unroll
                for (int ni = 0; ni < 4; ni++)
                    mma8(d[mi][ni], a[mi], b[ni]);
        }
        __syncthreads();                        // all reads of xs[buf] done

        // Stage D into the just-consumed x buffer as [c(128)][STW] (c-major rows).
        float* stg = reinterpret_cast<float*>(smem + bufoff);
        {
            float* sp = stg + (n0 + 2 * tm) * STW + m0 + t4;
#pragma unroll
            for (int ni = 0; ni < 4; ni++)
#pragma unroll
                for (int mi = 0; mi < 2; mi++) {
                    float* p = sp + ni * 8 * STW + mi * 16;
                    p[0]       = d[mi][ni][0];
                    p[STW]     = d[mi][ni][1];
                    p[8]       = d[mi][ni][2];
                    p[STW + 8] = d[mi][ni][3];
                }
        }
        __syncthreads();

        // Coalesced store: each warp writes 16 o-rows of 64 floats (256B) to outT[o][b].
        {
            const int b0 = browCTA + h * MH + 2 * lane;
            int cl = wid * 16;
            int o  = (INV81 * (c0 + cl)) & (IOF - 1);
#pragma unroll
            for (int i = 0; i < 16; i++) {
                float2 v = *reinterpret_cast<const float2*>(stg + (cl + i) * STW + 2 * lane);
                *reinterpret_cast<float2*>(g_outT + (size_t)o * BATCH + b0) = v;
                o = (o + INV81) & (IOF - 1);
            }
        }
        __syncthreads();                        // stage consumed before next prefetch overwrites it
    }
}

// ---------------- transpose + bias: out[b][o] = outT[o][b] + bias[o] ----------------
__global__ void transpose_kernel(const float* __restrict__ bias, float* __restrict__ out) {
    __shared__ float t[32][33];
    const int tx = threadIdx.x, ty = threadIdx.y;
    const int o0 = blockIdx.x * 32;
    const int b0 = blockIdx.y * 32;
#pragma unroll
    for (int k = ty; k < 32; k += 8)
        t[k][tx] = g_outT[(size_t)(o0 + k) * BATCH + b0 + tx];
    __syncthreads();
    float bv = bias[o0 + tx];
#pragma unroll
    for (int k = ty; k < 32; k += 8)
        out[(size_t)(b0 + k) * IOF + o0 + tx] = t[tx][k] + bv;
}

extern "C" void kernel_launch(void* const* d_in, const int* in_sizes, int n_in,
                              void* d_out, int out_size) {
    const float* x    = (const float*)d_in[0];
    const float* wgt  = (const float*)d_in[1];
    const float* bias = (const float*)d_in[2];
    const float* mask = (const float*)d_in[3];
    float* out = (float*)d_out;

    cudaFuncSetAttribute(main_kernel, cudaFuncAttributeMaxDynamicSharedMemorySize, SMEM_TOTAL);

    prep_kernel<<<(32 * KWIN * SB + 255) / 256, 256>>>(wgt, mask);
    main_kernel<<<dim3(32, GY), THREADS, SMEM_TOTAL>>>(x);
    transpose_kernel<<<dim3(IOF / 32, BATCH / 32), dim3(32, 8)>>>(bias, out);
}

// round 4
// speedup vs baseline: 3.4901x; 1.0139x over previous
#include <cuda_runtime.h>
#include <cstdint>

// StructuredConnection via warp-level tf32 mma.sync banded GEMM.
// c = 81*o mod 4096 <=> o = 2225*c mod 4096; in c-order: out_c = sum_j wp[c][j]*x[(c+j)&4095].
// CTA tile: M=32 batch rows x N=128 c. 8 warps, each a 16-wide c-slice -> per-warp K = 96.
// 4-deep cp.async pipeline on x (prefetch leads by 3 iters); B band tile loaded once.

#define BATCH   16384
#define IOF     4096
#define CPN     81
#define INV81   2225
#define NT      128          // c per CTA
#define MH      32           // batch rows per iter
#define KWIN    208          // k window per CTA tile
#define SX      212          // xs row stride (floats); 212%32==20 -> conflict-free A frags
#define SB      136          // Bs row stride (floats); 136%32==8  -> conflict-free B frags
#define ST      36           // stage row stride (floats); 16B-aligned rows
#define GY      4
#define NITER   128          // (BATCH/GY)/MH
#define THREADS 256
#define XS_BYTES (MH*SX*4)               // 27136
#define BS_BYTES (KWIN*SB*4)             // 113152
#define OFF_BS   (4*XS_BYTES)            // 108544
#define SMEM_TOTAL (4*XS_BYTES + BS_BYTES)   // 221696

__device__ uint32_t g_bw[32 * KWIN * SB];        // per-c-tile padded B (tf32 bits), [ct][k][n]
__device__ float    g_outT[(size_t)IOF * BATCH]; // transposed output: [o][b]

// ---------------- helpers ----------------
__device__ __forceinline__ uint32_t cvt_tf32(float x) {
    uint32_t u; asm("cvt.rna.tf32.f32 %0, %1;" : "=r"(u) : "f"(x)); return u;
}
__device__ __forceinline__ uint32_t smem_u32(const void* p) {
    uint32_t a; asm("{ .reg .u64 t; cvta.to.shared.u64 t, %1; cvt.u32.u64 %0, t; }" : "=r"(a) : "l"(p));
    return a;
}
#define CP16(d, s) asm volatile("cp.async.cg.shared.global [%0], [%1], 16;" :: "r"(d), "l"(s))
#define CPC()      asm volatile("cp.async.commit_group;" ::: "memory")
#define CPW2()     asm volatile("cp.async.wait_group 2;" ::: "memory")

__device__ __forceinline__ void mma8(float* d, const uint32_t* a, const uint32_t* b) {
    asm volatile(
        "mma.sync.aligned.m16n8k8.row.col.f32.tf32.tf32.f32 "
        "{%0,%1,%2,%3}, {%4,%5,%6,%7}, {%8,%9}, {%0,%1,%2,%3};"
        : "+f"(d[0]), "+f"(d[1]), "+f"(d[2]), "+f"(d[3])
        : "r"(a[0]), "r"(a[1]), "r"(a[2]), "r"(a[3]), "r"(b[0]), "r"(b[1]));
}

// ---------------- prep: tf32-rounded, band-expanded B in [ct][k][n] padded layout ----------------
__global__ void prep_kernel(const float* __restrict__ w, const float* __restrict__ m) {
    int idx = blockIdx.x * blockDim.x + threadIdx.x;
    if (idx >= 32 * KWIN * SB) return;
    int ct = idx / (KWIN * SB);
    int r  = idx - ct * (KWIN * SB);
    int k  = r / SB;
    int n  = r - k * SB;
    uint32_t u = 0;
    int j = k - n;
    if (n < NT && j >= 0 && j < CPN) {
        int c   = ct * NT + n;
        int o   = (INV81 * c) & (IOF - 1);
        int col = (c + j) & (IOF - 1);
        size_t off = (size_t)o * IOF + col;
        u = cvt_tf32(w[off] * m[off]);
    }
    g_bw[idx] = u;
}

// ---------------- main kernel ----------------
__global__ void __launch_bounds__(THREADS, 1) main_kernel(const float* __restrict__ x) {
    extern __shared__ char smem[];
    const uint32_t sb0 = smem_u32(smem);
    const int tid  = threadIdx.x;
    const int lane = tid & 31;
    const int wid  = tid >> 5;
    const int t4   = lane >> 2;     // 0..7
    const int tm   = lane & 3;      // 0..3
    const int ct   = blockIdx.x;
    const int c0   = ct * NT;
    const int browCTA = blockIdx.y * (BATCH / GY);

    // x tile loader: 32 rows x 208 floats (52 16B chunks/row), 1664 chunks = 6.5/thread.
    auto load_x = [&](int h) {
        const uint32_t dst = sb0 + (h & 3) * XS_BYTES;
        const int brow0 = browCTA + h * MH;
#pragma unroll
        for (int i = 0; i < 7; i++) {
            int q = i * THREADS + tid;
            if (q < MH * 52) {
                int row = q / 52;
                int chk = q - row * 52;
                const float* s = x + (size_t)(brow0 + row) * IOF + ((c0 + chk * 4) & (IOF - 1));
                CP16(dst + row * (SX * 4) + chk * 16, s);
            }
        }
    };

    // Prologue: B tile (straight 16B copy of pre-padded [208][136]) + x0 in group0; x1; x2.
    {
        const char* src = reinterpret_cast<const char*>(g_bw + (size_t)ct * KWIN * SB);
#pragma unroll
        for (int i = 0; i < 28; i++) {
            int q = i * THREADS + tid;
            if (q * 16 < BS_BYTES) CP16(sb0 + OFF_BS + q * 16, src + q * 16);
        }
    }
    load_x(0); CPC();
    load_x(1); CPC();
    load_x(2); CPC();

    const int n0w = wid * 16;       // warp's c-slice origin (also its k-window origin)

    for (int h = 0; h < NITER; h++) {
        CPW2();                     // x[h] (and B on h=0) resident
        __syncthreads();

        // Prefetch x[h+3] into buf[(h+3)&3] (freed: staged+stored during iter h-1).
        if (h + 3 < NITER) load_x(h + 3);
        CPC();

        const float*    xsb = reinterpret_cast<const float*>(smem + (h & 3) * XS_BYTES);
        const uint32_t* bsb = reinterpret_cast<const uint32_t*>(smem + OFF_BS);

        float d[2][2][4];
#pragma unroll
        for (int mi = 0; mi < 2; mi++)
#pragma unroll
            for (int ni = 0; ni < 2; ni++)
#pragma unroll
                for (int r = 0; r < 4; r++) d[mi][ni][r] = 0.0f;

#pragma unroll
        for (int s = 0; s < 12; s++) {          // per-warp K = 96
            const int kcol = n0w + s * 8 + tm;
            uint32_t a[2][4], b[2][2];
#pragma unroll
            for (int mi = 0; mi < 2; mi++) {
                const float* xp = xsb + (t4 + mi * 16) * SX + kcol;
                a[mi][0] = cvt_tf32(xp[0]);
                a[mi][1] = cvt_tf32(xp[8 * SX]);
                a[mi][2] = cvt_tf32(xp[4]);
                a[mi][3] = cvt_tf32(xp[8 * SX + 4]);
            }
            const uint32_t* bp = bsb + kcol * SB + n0w + t4;
#pragma unroll
            for (int ni = 0; ni < 2; ni++) {
                b[ni][0] = bp[ni * 8];
                b[ni][1] = bp[4 * SB + ni * 8];
            }
#pragma unroll
            for (int mi = 0; mi < 2; mi++)
#pragma unroll
                for (int ni = 0; ni < 2; ni++)
                    mma8(d[mi][ni], a[mi], b[ni]);
        }
        __syncthreads();                        // all reads of xs[h&3] done

        // Stage D into the just-consumed x buffer as [c(128)][ST] (c-major rows).
        float* stg = reinterpret_cast<float*>(smem + (h & 3) * XS_BYTES);
#pragma unroll
        for (int ni = 0; ni < 2; ni++)
#pragma unroll
            for (int mi = 0; mi < 2; mi++) {
                float* p = stg + (n0w + ni * 8 + 2 * tm) * ST + t4 + mi * 16;
                p[0]          = d[mi][ni][0];
                p[ST]         = d[mi][ni][1];
                p[8]          = d[mi][ni][2];
                p[ST + 8]     = d[mi][ni][3];
            }
        __syncthreads();

        // Coalesced store: warp w writes its 16 o-rows of 32 floats (128B) to outT[o][b].
        {
            const int b0 = browCTA + h * MH + lane;
            int o = (INV81 * (c0 + n0w)) & (IOF - 1);
#pragma unroll
            for (int i = 0; i < 16; i++) {
                g_outT[(size_t)o * BATCH + b0] = stg[(n0w + i) * ST + lane];
                o = (o + INV81) & (IOF - 1);
            }
        }
        __syncthreads();                        // stage consumed before buf reuse next iters
    }
}

// ---------------- transpose + bias: out[b][o] = outT[o][b] + bias[o] ----------------
__global__ void transpose_kernel(const float* __restrict__ bias, float* __restrict__ out) {
    __shared__ float t[32][33];
    const int tx = threadIdx.x, ty = threadIdx.y;
    const int o0 = blockIdx.x * 32;
    const int b0 = blockIdx.y * 32;
#pragma unroll
    for (int k = ty; k < 32; k += 8)
        t[k][tx] = g_outT[(size_t)(o0 + k) * BATCH + b0 + tx];
    __syncthreads();
    float bv = bias[o0 + tx];
#pragma unroll
    for (int k = ty; k < 32; k += 8)
        out[(size_t)(b0 + k) * IOF + o0 + tx] = t[tx][k] + bv;
}

extern "C" void kernel_launch(void* const* d_in, const int* in_sizes, int n_in,
                              void* d_out, int out_size) {
    const float* x    = (const float*)d_in[0];
    const float* wgt  = (const float*)d_in[1];
    const float* bias = (const float*)d_in[2];
    const float* mask = (const float*)d_in[3];
    float* out = (float*)d_out;

    cudaFuncSetAttribute(main_kernel, cudaFuncAttributeMaxDynamicSharedMemorySize, SMEM_TOTAL);

    prep_kernel<<<(32 * KWIN * SB + 255) / 256, 256>>>(wgt, mask);
    main_kernel<<<dim3(32, GY), THREADS, SMEM_TOTAL>>>(x);
    transpose_kernel<<<dim3(IOF / 32, BATCH / 32), dim3(32, 8)>>>(bias, out);
}

// round 7
// speedup vs baseline: 3.9638x; 1.1357x over previous
#include <cuda_runtime.h>
#include <cuda_fp16.h>
#include <cstdint>

// StructuredConnection via fp16 mma.sync banded GEMM (f32 accumulate).
// c = 81*o mod 4096 <=> o = 2225*c mod 4096; in c-order: out_c = sum_j wp[c][j]*x[(c+j)&4095].
// CTA tile: M=32 batch rows x N=128 c. 8 warps, each a 16-wide c-slice -> per-warp K = 96.
// B pair-packed along k: [k2 = k/2][n], n stride SBH=136 (>=128, conflict-free).

#define BATCH   16384
#define IOF     4096
#define CPN     81
#define INV81   2225
#define NT      128          // c per CTA
#define MH      32           // batch rows per iter
#define KWIN    208          // k window per CTA tile
#define SX      216          // xs row stride (floats); 216%32==24 -> conflict-free LDS.64 A frags
#define K2N     104          // KWIN/2 packed-k rows of B
#define SBH     136          // B row stride in u32 (f16x2); 136%32==8 -> conflict-free B frags
#define ST      36           // stage row stride (floats)
#define GY      8
#define NITER   64           // (BATCH/GY)/MH
#define THREADS 256
#define XS_BYTES (MH*SX*4)               // 27648
#define BH_BYTES (K2N*SBH*4)             // 56576
#define OFF_BS   (2*XS_BYTES)            // 55296
#define SMEM_TOTAL (2*XS_BYTES + BH_BYTES)   // 111872 -> 2 CTAs/SM

__device__ uint32_t g_bh[32 * K2N * SBH];        // per-c-tile B, f16x2 pairs (k,k+1): [ct][k2][n]
__device__ float    g_outT[(size_t)IOF * BATCH]; // transposed output: [o][b]

// ---------------- helpers ----------------
__device__ __forceinline__ uint32_t smem_u32(const void* p) {
    uint32_t a; asm("{ .reg .u64 t; cvta.to.shared.u64 t, %1; cvt.u32.u64 %0, t; }" : "=r"(a) : "l"(p));
    return a;
}
// pack two f32 -> f16x2 (lo = first arg in bits [15:0])
__device__ __forceinline__ uint32_t pack16(float lo, float hi) {
    uint32_t d; asm("cvt.rn.f16x2.f32 %0, %1, %2;" : "=r"(d) : "f"(hi), "f"(lo)); return d;
}
#define CP16(d, s) asm volatile("cp.async.cg.shared.global [%0], [%1], 16;" :: "r"(d), "l"(s))
#define CPC()      asm volatile("cp.async.commit_group;" ::: "memory")
#define CPW1()     asm volatile("cp.async.wait_group 1;" ::: "memory")

__device__ __forceinline__ void mma16(float* d, const uint32_t* a, const uint32_t* b) {
    asm volatile(
        "mma.sync.aligned.m16n8k16.row.col.f32.f16.f16.f32 "
        "{%0,%1,%2,%3}, {%4,%5,%6,%7}, {%8,%9}, {%0,%1,%2,%3};"
        : "+f"(d[0]), "+f"(d[1]), "+f"(d[2]), "+f"(d[3])
        : "r"(a[0]), "r"(a[1]), "r"(a[2]), "r"(a[3]), "r"(b[0]), "r"(b[1]));
}

// ---------------- prep: fp16-paired, band-expanded B in [ct][k2][n(SBH)] layout ----------------
__global__ void prep_kernel(const float* __restrict__ w, const float* __restrict__ m) {
    int idx = blockIdx.x * blockDim.x + threadIdx.x;
    if (idx >= 32 * K2N * SBH) return;
    int ct = idx / (K2N * SBH);
    int r  = idx - ct * (K2N * SBH);
    int k2 = r / SBH;
    int n  = r - k2 * SBH;
    uint32_t u = 0;
    if (n < NT) {
#pragma unroll
        for (int half = 0; half < 2; half++) {
            int k = 2 * k2 + half;
            int j = k - n;
            if (j >= 0 && j < CPN && k < KWIN) {
                int c   = ct * NT + n;
                int o   = (INV81 * c) & (IOF - 1);
                int col = (c + j) & (IOF - 1);
                size_t off = (size_t)o * IOF + col;
                float v = w[off] * m[off];
                uint32_t hb = (uint32_t)__half_as_ushort(__float2half_rn(v));
                u |= hb << (16 * half);
            }
        }
    }
    g_bh[idx] = u;
}

// ---------------- main kernel ----------------
__global__ void __launch_bounds__(THREADS, 2) main_kernel(const float* __restrict__ x) {
    extern __shared__ char smem[];
    const uint32_t sb0 = smem_u32(smem);
    const int tid  = threadIdx.x;
    const int lane = tid & 31;
    const int wid  = tid >> 5;
    const int t4   = lane >> 2;     // 0..7
    const int tm   = lane & 3;      // 0..3
    const int ct   = blockIdx.x;
    const int c0   = ct * NT;
    const int browCTA = blockIdx.y * (BATCH / GY);

    // x tile loader: 32 rows x 208 floats (52 16B chunks/row), 1664 chunks.
    auto load_x = [&](int h) {
        const uint32_t dst = sb0 + (h & 1) * XS_BYTES;
        const int brow0 = browCTA + h * MH;
#pragma unroll
        for (int i = 0; i < 7; i++) {
            int q = i * THREADS + tid;
            if (q < MH * 52) {
                int row = q / 52;
                int chk = q - row * 52;
                const float* s = x + (size_t)(brow0 + row) * IOF + ((c0 + chk * 4) & (IOF - 1));
                CP16(dst + row * (SX * 4) + chk * 16, s);
            }
        }
    };

    // Prologue: B tile (straight copy of pre-packed [104][136] u32, 3536 chunks) + x0; x1.
    {
        const char* src = reinterpret_cast<const char*>(g_bh + (size_t)ct * K2N * SBH);
#pragma unroll
        for (int i = 0; i < 14; i++) {
            int q = i * THREADS + tid;
            if (q * 16 < BH_BYTES) CP16(sb0 + OFF_BS + q * 16, src + q * 16);
        }
    }
    load_x(0); CPC();
    load_x(1); CPC();

    const int n0w = wid * 16;       // warp's c-slice origin (also its k-window origin)
    const uint32_t* bh = reinterpret_cast<const uint32_t*>(smem + OFF_BS);

    for (int h = 0; h < NITER; h++) {
        CPW1();                     // x[h] (and B on h=0) resident
        __syncthreads();

        const float* xsb = reinterpret_cast<const float*>(smem + (h & 1) * XS_BYTES)
                         + t4 * SX + n0w + 2 * tm;

        float d[2][2][4];
#pragma unroll
        for (int mi = 0; mi < 2; mi++)
#pragma unroll
            for (int ni = 0; ni < 2; ni++)
#pragma unroll
                for (int r = 0; r < 4; r++) d[mi][ni][r] = 0.0f;

#pragma unroll
        for (int s = 0; s < 6; s++) {           // per-warp K = 96, 16 per step
            const int kb = s * 16;
            uint32_t a[2][4], b[2][2];
#pragma unroll
            for (int mi = 0; mi < 2; mi++) {
                const float* xp = xsb + mi * 16 * SX + kb;
                float2 v0 = *reinterpret_cast<const float2*>(xp);
                float2 v1 = *reinterpret_cast<const float2*>(xp + 8 * SX);
                float2 v2 = *reinterpret_cast<const float2*>(xp + 8);
                float2 v3 = *reinterpret_cast<const float2*>(xp + 8 * SX + 8);
                a[mi][0] = pack16(v0.x, v0.y);
                a[mi][1] = pack16(v1.x, v1.y);
                a[mi][2] = pack16(v2.x, v2.y);
                a[mi][3] = pack16(v3.x, v3.y);
            }
            // B packed-k row: k2 = n0w/2 (warp window origin) + s*8 + tm; col = n0w + t4 (+8).
            const uint32_t* bp = bh + ((n0w >> 1) + s * 8 + tm) * SBH + n0w + t4;
#pragma unroll
            for (int ni = 0; ni < 2; ni++) {
                b[ni][0] = bp[ni * 8];
                b[ni][1] = bp[4 * SBH + ni * 8];
            }
#pragma unroll
            for (int mi = 0; mi < 2; mi++)
#pragma unroll
                for (int ni = 0; ni < 2; ni++)
                    mma16(d[mi][ni], a[mi], b[ni]);
        }
        __syncthreads();                        // all reads of xs[h&1] done

        // Stage D into the just-consumed x buffer as [c(128)][ST] (c-major rows).
        float* stg = reinterpret_cast<float*>(smem + (h & 1) * XS_BYTES);
#pragma unroll
        for (int ni = 0; ni < 2; ni++)
#pragma unroll
            for (int mi = 0; mi < 2; mi++) {
                float* p = stg + (n0w + ni * 8 + 2 * tm) * ST + t4 + mi * 16;
                p[0]      = d[mi][ni][0];
                p[ST]     = d[mi][ni][1];
                p[8]      = d[mi][ni][2];
                p[ST + 8] = d[mi][ni][3];
            }
        __syncthreads();

        // Coalesced store: warp w writes its 16 o-rows of 32 floats (128B) to outT[o][b].
        {
            const int b0 = browCTA + h * MH + lane;
            int o = (INV81 * (c0 + n0w)) & (IOF - 1);
#pragma unroll
            for (int i = 0; i < 16; i++) {
                g_outT[(size_t)o * BATCH + b0] = stg[(n0w + i) * ST + lane];
                o = (o + INV81) & (IOF - 1);
            }
        }
        __syncthreads();                        // stage fully consumed

        // Prefetch x[h+2] into buf[h&1] (now free); lands during iter h+1.
        if (h + 2 < NITER) load_x(h + 2);
        CPC();
    }
}

// ---------------- transpose + bias: out[b][o] = outT[o][b] + bias[o] ----------------
__global__ void transpose_kernel(const float* __restrict__ bias, float* __restrict__ out) {
    __shared__ float t[32][33];
    const int tx = threadIdx.x, ty = threadIdx.y;
    const int o0 = blockIdx.x * 32;
    const int b0 = blockIdx.y * 32;
#pragma unroll
    for (int k = ty; k < 32; k += 8)
        t[k][tx] = g_outT[(size_t)(o0 + k) * BATCH + b0 + tx];
    __syncthreads();
    float bv = bias[o0 + tx];
#pragma unroll
    for (int k = ty; k < 32; k += 8)
        out[(size_t)(b0 + k) * IOF + o0 + tx] = t[tx][k] + bv;
}

extern "C" void kernel_launch(void* const* d_in, const int* in_sizes, int n_in,
                              void* d_out, int out_size) {
    const float* x    = (const float*)d_in[0];
    const float* wgt  = (const float*)d_in[1];
    const float* bias = (const float*)d_in[2];
    const float* mask = (const float*)d_in[3];
    float* out = (float*)d_out;

    cudaFuncSetAttribute(main_kernel, cudaFuncAttributeMaxDynamicSharedMemorySize, SMEM_TOTAL);

    prep_kernel<<<(32 * K2N * SBH + 255) / 256, 256>>>(wgt, mask);
    main_kernel<<<dim3(32, GY), THREADS, SMEM_TOTAL>>>(x);
    transpose_kernel<<<dim3(IOF / 32, BATCH / 32), dim3(32, 8)>>>(bias, out);
}

// round 8
// speedup vs baseline: 4.1692x; 1.0518x over previous
#include <cuda_runtime.h>
#include <cuda_fp16.h>
#include <cstdint>

// StructuredConnection via fp16 mma.sync banded GEMM (f32 accumulate).
// c = 81*o mod 4096 <=> o = 2225*c mod 4096; in c-order: out_c = sum_j wp[c][j]*x[(c+j)&4095].
// CTA tile: M=32 batch rows x N=128 c. 8 warps, each a 16-wide c-slice -> per-warp K = 96.
// B fragments live in REGISTERS (loop-invariant); D stored straight to g_outT (32B segments).
// 4-deep cp.async x ring, ONE barrier per iteration.

#define BATCH   16384
#define IOF     4096
#define CPN     81
#define INV81   2225
#define NT      128          // c per CTA
#define MH      32           // batch rows per iter
#define KWIN    208          // k window per CTA tile
#define SX      216          // xs row stride (floats); 216%32==24 -> conflict-free LDS.64 A frags
#define K2N     104          // KWIN/2 packed-k rows of B
#define SBH     136          // B row stride in u32 (f16x2)
#define GY      8
#define NITER   64           // (BATCH/GY)/MH
#define THREADS 256
#define XS_BYTES (MH*SX*4)               // 27648
#define SMEM_TOTAL (4*XS_BYTES)          // 110592 -> 2 CTAs/SM

__device__ uint32_t g_bh[32 * K2N * SBH];        // per-c-tile B, f16x2 pairs (k,k+1): [ct][k2][n]
__device__ float    g_outT[(size_t)IOF * BATCH]; // transposed output: [o][b]

// ---------------- helpers ----------------
__device__ __forceinline__ uint32_t smem_u32(const void* p) {
    uint32_t a; asm("{ .reg .u64 t; cvta.to.shared.u64 t, %1; cvt.u32.u64 %0, t; }" : "=r"(a) : "l"(p));
    return a;
}
// pack two f32 -> f16x2 (lo = first arg in bits [15:0])
__device__ __forceinline__ uint32_t pack16(float lo, float hi) {
    uint32_t d; asm("cvt.rn.f16x2.f32 %0, %1, %2;" : "=r"(d) : "f"(hi), "f"(lo)); return d;
}
#define CP16(d, s) asm volatile("cp.async.cg.shared.global [%0], [%1], 16;" :: "r"(d), "l"(s))
#define CPC()      asm volatile("cp.async.commit_group;" ::: "memory")
#define CPW()      asm volatile("cp.async.wait_group 2;" ::: "memory")

__device__ __forceinline__ void mma16(float* d, const uint32_t* a, const uint32_t* b) {
    asm volatile(
        "mma.sync.aligned.m16n8k16.row.col.f32.f16.f16.f32 "
        "{%0,%1,%2,%3}, {%4,%5,%6,%7}, {%8,%9}, {%0,%1,%2,%3};"
        : "+f"(d[0]), "+f"(d[1]), "+f"(d[2]), "+f"(d[3])
        : "r"(a[0]), "r"(a[1]), "r"(a[2]), "r"(a[3]), "r"(b[0]), "r"(b[1]));
}

// ---------------- prep: fp16-paired, band-expanded B in [ct][k2][n(SBH)] layout ----------------
__global__ void prep_kernel(const float* __restrict__ w, const float* __restrict__ m) {
    int idx = blockIdx.x * blockDim.x + threadIdx.x;
    if (idx >= 32 * K2N * SBH) return;
    int ct = idx / (K2N * SBH);
    int r  = idx - ct * (K2N * SBH);
    int k2 = r / SBH;
    int n  = r - k2 * SBH;
    uint32_t u = 0;
    if (n < NT) {
#pragma unroll
        for (int half = 0; half < 2; half++) {
            int k = 2 * k2 + half;
            int j = k - n;
            if (j >= 0 && j < CPN && k < KWIN) {
                int c   = ct * NT + n;
                int o   = (INV81 * c) & (IOF - 1);
                int col = (c + j) & (IOF - 1);
                size_t off = (size_t)o * IOF + col;
                float v = w[off] * m[off];
                uint32_t hb = (uint32_t)__half_as_ushort(__float2half_rn(v));
                u |= hb << (16 * half);
            }
        }
    }
    g_bh[idx] = u;
}

// ---------------- main kernel ----------------
__global__ void __launch_bounds__(THREADS, 2) main_kernel(const float* __restrict__ x) {
    extern __shared__ char smem[];
    const uint32_t sb0 = smem_u32(smem);
    const int tid  = threadIdx.x;
    const int lane = tid & 31;
    const int wid  = tid >> 5;
    const int t4   = lane >> 2;     // 0..7
    const int tm   = lane & 3;      // 0..3
    const int ct   = blockIdx.x;
    const int c0   = ct * NT;
    const int browCTA = blockIdx.y * (BATCH / GY);
    const int n0w  = wid * 16;      // warp's c-slice origin (also its k-window origin)

    // x tile loader: 32 rows x 208 floats (52 16B chunks/row), 1664 chunks, 4-buffer ring.
    auto load_x = [&](int h) {
        const uint32_t dst = sb0 + (h & 3) * XS_BYTES;
        const int brow0 = browCTA + h * MH;
#pragma unroll
        for (int i = 0; i < 7; i++) {
            int q = i * THREADS + tid;
            if (q < MH * 52) {
                int row = q / 52;
                int chk = q - row * 52;
                const float* s = x + (size_t)(brow0 + row) * IOF + ((c0 + chk * 4) & (IOF - 1));
                CP16(dst + row * (SX * 4) + chk * 16, s);
            }
        }
    };

    // B fragments into registers once (loop-invariant across all 64 iterations).
    uint32_t breg[24];
    {
        const uint32_t* bg = g_bh + (size_t)ct * K2N * SBH;
#pragma unroll
        for (int s = 0; s < 6; s++) {
            const uint32_t* bp = bg + ((n0w >> 1) + s * 8 + tm) * SBH + n0w + t4;
#pragma unroll
            for (int ni = 0; ni < 2; ni++) {
                breg[s * 4 + ni * 2 + 0] = __ldg(bp + ni * 8);
                breg[s * 4 + ni * 2 + 1] = __ldg(bp + 4 * SBH + ni * 8);
            }
        }
    }
    // Loop-invariant output row offsets: oB[ni][p] = o(c)*BATCH for this thread's 4 columns.
    uint32_t oB[2][2];
#pragma unroll
    for (int ni = 0; ni < 2; ni++)
#pragma unroll
        for (int p = 0; p < 2; p++) {
            int c = c0 + n0w + 8 * ni + 2 * tm + p;
            oB[ni][p] = (uint32_t)((INV81 * c) & (IOF - 1)) * BATCH;
        }

    load_x(0); CPC();
    load_x(1); CPC();
    load_x(2); CPC();

    for (int h = 0; h < NITER; h++) {
        CPW();                      // group h complete (<=2 pending: h+1, h+2)
        __syncthreads();            // all threads' x[h] chunks visible; buf[(h+3)&3] free

        const float* xsb = reinterpret_cast<const float*>(smem + (h & 3) * XS_BYTES)
                         + t4 * SX + n0w + 2 * tm;

        float d[2][2][4];
#pragma unroll
        for (int mi = 0; mi < 2; mi++)
#pragma unroll
            for (int ni = 0; ni < 2; ni++)
#pragma unroll
                for (int r = 0; r < 4; r++) d[mi][ni][r] = 0.0f;

#pragma unroll
        for (int s = 0; s < 6; s++) {           // per-warp K = 96, 16 per step
            const int kb = s * 16;
            uint32_t a[2][4];
#pragma unroll
            for (int mi = 0; mi < 2; mi++) {
                const float* xp = xsb + mi * 16 * SX + kb;
                float2 v0 = *reinterpret_cast<const float2*>(xp);
                float2 v1 = *reinterpret_cast<const float2*>(xp + 8 * SX);
                float2 v2 = *reinterpret_cast<const float2*>(xp + 8);
                float2 v3 = *reinterpret_cast<const float2*>(xp + 8 * SX + 8);
                a[mi][0] = pack16(v0.x, v0.y);
                a[mi][1] = pack16(v1.x, v1.y);
                a[mi][2] = pack16(v2.x, v2.y);
                a[mi][3] = pack16(v3.x, v3.y);
            }
#pragma unroll
            for (int mi = 0; mi < 2; mi++)
#pragma unroll
                for (int ni = 0; ni < 2; ni++)
                    mma16(d[mi][ni], a[mi], &breg[s * 4 + ni * 2]);
        }

        // Direct store: 8 lanes (t4) x 4B contiguous along b => full 32B sectors, 4 rows per STG.
        {
            const int bb = browCTA + h * MH + t4;
#pragma unroll
            for (int mi = 0; mi < 2; mi++)
#pragma unroll
                for (int ni = 0; ni < 2; ni++) {
                    float* p0 = g_outT + (size_t)oB[ni][0] + bb + 16 * mi;
                    p0[0] = d[mi][ni][0];
                    p0[8] = d[mi][ni][2];
                    float* p1 = g_outT + (size_t)oB[ni][1] + bb + 16 * mi;
                    p1[0] = d[mi][ni][1];
                    p1[8] = d[mi][ni][3];
                }
        }

        // Prefetch x[h+3] into buf[(h+3)&3] (its last readers finished before barrier h).
        if (h + 3 < NITER) load_x(h + 3);
        CPC();
    }
}

// ---------------- transpose + bias: out[b][o] = outT[o][b] + bias[o] ----------------
__global__ void transpose_kernel(const float* __restrict__ bias, float* __restrict__ out) {
    __shared__ float t[32][33];
    const int tx = threadIdx.x, ty = threadIdx.y;
    const int o0 = blockIdx.x * 32;
    const int b0 = blockIdx.y * 32;
#pragma unroll
    for (int k = ty; k < 32; k += 8)
        t[k][tx] = g_outT[(size_t)(o0 + k) * BATCH + b0 + tx];
    __syncthreads();
    float bv = bias[o0 + tx];
#pragma unroll
    for (int k = ty; k < 32; k += 8)
        out[(size_t)(b0 + k) * IOF + o0 + tx] = t[tx][k] + bv;
}

extern "C" void kernel_launch(void* const* d_in, const int* in_sizes, int n_in,
                              void* d_out, int out_size) {
    const float* x    = (const float*)d_in[0];
    const float* wgt  = (const float*)d_in[1];
    const float* bias = (const float*)d_in[2];
    const float* mask = (const float*)d_in[3];
    float* out = (float*)d_out;

    cudaFuncSetAttribute(main_kernel, cudaFuncAttributeMaxDynamicSharedMemorySize, SMEM_TOTAL);

    prep_kernel<<<(32 * K2N * SBH + 255) / 256, 256>>>(wgt, mask);
    main_kernel<<<dim3(32, GY), THREADS, SMEM_TOTAL>>>(x);
    transpose_kernel<<<dim3(IOF / 32, BATCH / 32), dim3(32, 8)>>>(bias, out);
}